// round 15
// baseline (speedup 1.0000x reference)
#include <cuda_runtime.h>
#include <cuda_bf16.h>

// DiffJPEG per-8x8-block: out = D^T . Qnt( D . (X . D^T) ) . D
// R15: row-split warp pairs. Warp 2k (h=0) owns rows 0-3, warp 2k+1 rows 4-7
// of the same 32 blocks (lane <-> block). Row transforms are local and fully
// coalesced (32B/lane contiguous). The column-local middle (col-fwd, quant,
// col-inv) runs col-split after a smem exchange; h is WARP-uniform so quant
// constants are compile-time immediates (no per-lane SELs, R14's win) while
// global I/O stays R12-coalesced. Per-pair named barriers decouple pairs.

using u64 = unsigned long long;

// D[i][j] = c_i * cos((2j+1) i pi / 16), c_0 = sqrt(1/8), else 0.5
__device__ constexpr float DMc[8][8] = {
    { 0.3535533905932738f,  0.3535533905932738f,  0.3535533905932738f,  0.3535533905932738f,
      0.3535533905932738f,  0.3535533905932738f,  0.3535533905932738f,  0.3535533905932738f },
    { 0.4903926402016152f,  0.4157348061512726f,  0.2777851165098011f,  0.0975451610080642f,
     -0.0975451610080642f, -0.2777851165098011f, -0.4157348061512726f, -0.4903926402016152f },
    { 0.4619397662556434f,  0.1913417161825449f, -0.1913417161825449f, -0.4619397662556434f,
     -0.4619397662556434f, -0.1913417161825449f,  0.1913417161825449f,  0.4619397662556434f },
    { 0.4157348061512726f, -0.0975451610080642f, -0.4903926402016152f, -0.2777851165098011f,
      0.2777851165098011f,  0.4903926402016152f,  0.0975451610080642f, -0.4157348061512726f },
    { 0.3535533905932738f, -0.3535533905932738f, -0.3535533905932738f,  0.3535533905932738f,
      0.3535533905932738f, -0.3535533905932738f, -0.3535533905932738f,  0.3535533905932738f },
    { 0.2777851165098011f, -0.4903926402016152f,  0.0975451610080642f,  0.4157348061512726f,
     -0.4157348061512726f, -0.0975451610080642f,  0.4903926402016152f, -0.2777851165098011f },
    { 0.1913417161825449f, -0.4619397662556434f,  0.4619397662556434f, -0.1913417161825449f,
     -0.1913417161825449f,  0.4619397662556434f, -0.4619397662556434f,  0.1913417161825449f },
    { 0.0975451610080642f, -0.2777851165098011f,  0.4157348061512726f, -0.4903926402016152f,
      0.4903926402016152f, -0.4157348061512726f,  0.2777851165098011f, -0.0975451610080642f },
};

// quality=50 -> Q == q_luma exactly.
__device__ constexpr float QMc[8][8] = {
    { 16.f, 11.f, 10.f, 16.f,  24.f,  40.f,  51.f,  61.f },
    { 12.f, 12.f, 14.f, 19.f,  26.f,  58.f,  60.f,  55.f },
    { 14.f, 13.f, 16.f, 24.f,  40.f,  57.f,  69.f,  56.f },
    { 14.f, 17.f, 22.f, 29.f,  51.f,  87.f,  80.f,  62.f },
    { 18.f, 22.f, 37.f, 56.f,  68.f, 109.f, 103.f,  77.f },
    { 24.f, 35.f, 55.f, 64.f,  81.f, 104.f, 113.f,  92.f },
    { 49.f, 64.f, 78.f, 87.f, 103.f, 121.f, 120.f, 101.f },
    { 72.f, 92.f, 95.f, 98.f, 112.f, 100.f, 103.f,  99.f },
};

__device__ __forceinline__ u64 pk(float a, float b) {
    u64 r; asm("mov.b64 %0, {%1, %2};" : "=l"(r) : "f"(a), "f"(b)); return r;
}
__device__ __forceinline__ void unpk(float& a, float& b, u64 v) {
    asm("mov.b64 {%0, %1}, %2;" : "=f"(a), "=f"(b) : "l"(v));
}
__device__ __forceinline__ u64 fma2(u64 a, u64 b, u64 c) {
    u64 d; asm("fma.rn.f32x2 %0, %1, %2, %3;" : "=l"(d) : "l"(a), "l"(b), "l"(c)); return d;
}
__device__ __forceinline__ u64 mul2(u64 a, u64 b) {
    u64 d; asm("mul.rn.f32x2 %0, %1, %2;" : "=l"(d) : "l"(a), "l"(b)); return d;
}
__device__ __forceinline__ u64 add2(u64 a, u64 b) {
    u64 d; asm("add.rn.f32x2 %0, %1, %2;" : "=l"(d) : "l"(a), "l"(b)); return d;
}
__device__ __forceinline__ u64 sub2(u64 a, u64 b, u64 neg1) {
    return fma2(b, neg1, a);   // a - b
}

// forward row transform: x = (x0,x1)(x2,x3)(x4,x5)(x6,x7) -> y = X.D^T pairs
__device__ __forceinline__ void row_fwd(const u64 (&x)[4], u64 (&y)[4]) {
    float a0,a1,a2,a3,a4,a5,a6,a7;
    unpk(a0, a1, x[0]); unpk(a2, a3, x[1]);
    unpk(a4, a5, x[2]); unpk(a6, a7, x[3]);
    u64 sd[4];
    sd[0] = pk(a0 + a7, a0 - a7);
    sd[1] = pk(a1 + a6, a1 - a6);
    sd[2] = pk(a2 + a5, a2 - a5);
    sd[3] = pk(a3 + a4, a3 - a4);
    #pragma unroll
    for (int t = 0; t < 4; ++t) {
        u64 acc = mul2(sd[0], pk(DMc[2*t][0], DMc[2*t+1][0]));
        #pragma unroll
        for (int j = 1; j < 4; ++j)
            acc = fma2(sd[j], pk(DMc[2*t][j], DMc[2*t+1][j]), acc);
        y[t] = acc;
    }
}

// inverse row transform: w (8 values) -> o = W.D pairs, via even/odd butterfly
__device__ __forceinline__ void row_inv(const u64 (&w)[4], u64 (&o)[4], u64 NEG1) {
    float m0,m1,m2,m3,m4,m5,m6,m7;
    unpk(m0, m1, w[0]); unpk(m2, m3, w[1]);
    unpk(m4, m5, w[2]); unpk(m6, m7, w[3]);
    u64 U01 = mul2(pk(m0, m0), pk(DMc[0][0], DMc[0][1]));
    u64 U23 = mul2(pk(m0, m0), pk(DMc[0][2], DMc[0][3]));
    u64 V01 = mul2(pk(m1, m1), pk(DMc[1][0], DMc[1][1]));
    u64 V23 = mul2(pk(m1, m1), pk(DMc[1][2], DMc[1][3]));
    const float me[3] = { m2, m4, m6 };
    const float mo[3] = { m3, m5, m7 };
    #pragma unroll
    for (int t = 1; t < 4; ++t) {
        u64 be = pk(me[t-1], me[t-1]);
        U01 = fma2(be, pk(DMc[2*t][0], DMc[2*t][1]), U01);
        U23 = fma2(be, pk(DMc[2*t][2], DMc[2*t][3]), U23);
        u64 bo = pk(mo[t-1], mo[t-1]);
        V01 = fma2(bo, pk(DMc[2*t+1][0], DMc[2*t+1][1]), V01);
        V23 = fma2(bo, pk(DMc[2*t+1][2], DMc[2*t+1][3]), V23);
    }
    o[0] = add2(U01, V01);             // (P0, P1)
    o[1] = add2(U23, V23);             // (P2, P3)
    u64 t76 = sub2(U01, V01, NEG1);    // (P7, P6)
    u64 t54 = sub2(U23, V23, NEG1);    // (P5, P4)
    { float x, y; unpk(x, y, t54); o[2] = pk(y, x); }  // (P4, P5)
    { float x, y; unpk(x, y, t76); o[3] = pk(y, x); }  // (P6, P7)
}

// packed quant/dequant of A[8][2] covering columns C..C+3 (C compile-time)
template<int C>
__device__ __forceinline__ void quant_cols(u64 (&A)[8][2], u64 NEG1, u64 MAGIC2) {
    #pragma unroll
    for (int i = 0; i < 8; ++i) {
        #pragma unroll
        for (int k = 0; k < 2; ++k) {
            u64 sc = mul2(A[i][k], pk(1.0f / QMc[i][C+2*k], 1.0f / QMc[i][C+2*k+1]));
            u64 rr = add2(sc, MAGIC2);
            rr = sub2(rr, MAGIC2, NEG1);
            A[i][k] = mul2(rr, pk(QMc[i][C+2*k], QMc[i][C+2*k+1]));
        }
    }
}

#define PAIR_BAR() asm volatile("bar.sync %0, 64;" :: "r"(pr + 1) : "memory")

__global__ void __launch_bounds__(256, 4)
diffjpeg_kernel(const float* __restrict__ in, float* __restrict__ out, int nblk)
{
    // exchange stage per warp-pair: [row][block(lane)][colpair], u64 units
    __shared__ __align__(16) u64 xb[4][8][32][4];      // 32 KB

    const int tid  = threadIdx.x;
    const int w    = tid >> 5;
    const int lane = tid & 31;
    const int h    = w & 1;          // warp-uniform: row half (and col half mid-phase)
    const int pr   = w >> 1;         // pair id 0..3

    int blk = blockIdx.x * 128 + pr * 32 + lane;
    if (blk >= nblk) blk = nblk - 1;               // duplicate tail writes: benign

    const u64 NEG1   = pk(-1.0f, -1.0f);
    const u64 MAGIC2 = pk(12582912.0f, 12582912.0f);   // 1.5 * 2^23

    int bw  = blk & 63;
    int t1  = blk >> 6;
    int bh  = t1 & 63;
    int img = t1 >> 6;
    size_t base = ((size_t)img << 18) + ((size_t)bh << 12) + ((size_t)bw << 3);
    const float* p = in  + base;
    float*       q = out + base;

    u64 (*X)[32][4] = xb[pr];

    // ---- load my 4 rows (coalesced), row-fwd, stage to smem ---------------
    {
        u64 x[4][4];
        #pragma unroll
        for (int r = 0; r < 4; ++r) {
            const ulonglong2* rp =
                reinterpret_cast<const ulonglong2*>(p + (size_t)(4*h + r) * 512);
            ulonglong2 a = __ldcs(rp), b = __ldcs(rp + 1);
            x[r][0] = a.x; x[r][1] = a.y; x[r][2] = b.x; x[r][3] = b.y;
        }
        #pragma unroll
        for (int r = 0; r < 4; ++r) {
            u64 y[4];
            row_fwd(x[r], y);
            *reinterpret_cast<ulonglong2*>(&X[4*h + r][lane][0]) = make_ulonglong2(y[0], y[1]);
            *reinterpret_cast<ulonglong2*>(&X[4*h + r][lane][2]) = make_ulonglong2(y[2], y[3]);
        }
    }
    PAIR_BAR();

    // ---- col-split middle: col-fwd butterfly over rows --------------------
    const int ch = 2 * h;                          // my colpair base (warp-uniform)
    u64 A[8][2];
    #pragma unroll
    for (int t = 0; t < 4; ++t) {
        ulonglong2 yt = *reinterpret_cast<const ulonglong2*>(&X[t][lane][ch]);
        ulonglong2 yb = *reinterpret_cast<const ulonglong2*>(&X[7 - t][lane][ch]);
        u64 S0 = add2(yt.x, yb.x),       S1 = add2(yt.y, yb.y);
        u64 D0 = sub2(yt.x, yb.x, NEG1), D1 = sub2(yt.y, yb.y, NEG1);
        #pragma unroll
        for (int u = 0; u < 4; ++u) {
            u64 ce = pk(DMc[2*u][t],   DMc[2*u][t]);
            u64 co = pk(DMc[2*u+1][t], DMc[2*u+1][t]);
            if (t == 0) {
                A[2*u][0]   = mul2(ce, S0);  A[2*u][1]   = mul2(ce, S1);
                A[2*u+1][0] = mul2(co, D0);  A[2*u+1][1] = mul2(co, D1);
            } else {
                A[2*u][0]   = fma2(ce, S0, A[2*u][0]);   A[2*u][1]   = fma2(ce, S1, A[2*u][1]);
                A[2*u+1][0] = fma2(co, D0, A[2*u+1][0]); A[2*u+1][1] = fma2(co, D1, A[2*u+1][1]);
            }
        }
    }
    PAIR_BAR();                                    // all reads done before rewrite

    // ---- quant/dequant: columns 4h..4h+3, constants are immediates --------
    if (h == 0) quant_cols<0>(A, NEG1, MAGIC2);
    else        quant_cols<4>(A, NEG1, MAGIC2);

    // ---- col-inv butterfly, write rows back to stage ----------------------
    #pragma unroll
    for (int i = 0; i < 4; ++i) {
        u64 u0, u1, v0, v1;
        {
            u64 ce = pk(DMc[0][i], DMc[0][i]);
            u64 co = pk(DMc[1][i], DMc[1][i]);
            u0 = mul2(ce, A[0][0]); u1 = mul2(ce, A[0][1]);
            v0 = mul2(co, A[1][0]); v1 = mul2(co, A[1][1]);
        }
        #pragma unroll
        for (int t = 1; t < 4; ++t) {
            u64 ce = pk(DMc[2*t][i], DMc[2*t][i]);
            u64 co = pk(DMc[2*t+1][i], DMc[2*t+1][i]);
            u0 = fma2(ce, A[2*t][0], u0);   u1 = fma2(ce, A[2*t][1], u1);
            v0 = fma2(co, A[2*t+1][0], v0); v1 = fma2(co, A[2*t+1][1], v1);
        }
        *reinterpret_cast<ulonglong2*>(&X[i][lane][ch]) =
            make_ulonglong2(add2(u0, v0), add2(u1, v1));
        *reinterpret_cast<ulonglong2*>(&X[7 - i][lane][ch]) =
            make_ulonglong2(sub2(u0, v0, NEG1), sub2(u1, v1, NEG1));
    }
    PAIR_BAR();

    // ---- back to row-split: row-inv my 4 rows, store coalesced ------------
    #pragma unroll
    for (int r = 0; r < 4; ++r) {
        ulonglong2 wa = *reinterpret_cast<const ulonglong2*>(&X[4*h + r][lane][0]);
        ulonglong2 wb = *reinterpret_cast<const ulonglong2*>(&X[4*h + r][lane][2]);
        u64 wrow[4] = { wa.x, wa.y, wb.x, wb.y };
        u64 o[4];
        row_inv(wrow, o, NEG1);
        ulonglong2* op = reinterpret_cast<ulonglong2*>(q + (size_t)(4*h + r) * 512);
        __stcs(op,     make_ulonglong2(o[0], o[1]));
        __stcs(op + 1, make_ulonglong2(o[2], o[3]));
    }
}

extern "C" void kernel_launch(void* const* d_in, const int* in_sizes, int n_in,
                              void* d_out, int out_size)
{
    const float* in  = (const float*)d_in[0];
    float*       out = (float*)d_out;
    int nblk = in_sizes[0] / 64;                  // number of 8x8 blocks
    int grid = (nblk + 127) / 128;                // 128 blocks per CTA (4 warp-pairs)
    diffjpeg_kernel<<<grid, 256>>>(in, out, nblk);
}

// round 17
// speedup vs baseline: 1.0998x; 1.0998x over previous
#include <cuda_runtime.h>
#include <cuda_bf16.h>

// DiffJPEG per-8x8-block: out = D^T . Qnt( D . (X . D^T) ) . D
// R16 (resubmit; previous run died to container infra failure):
// R15 row-split warp pairs (coalesced I/O + warp-uniform h -> zero per-lane
// SELs) + XOR chunk swizzle on the smem stage (kills R15's 2-way bank
// conflicts) + fused 3-op magic quant.
// Swizzle: physical 16B chunk = logical ^ ((lane>>2)&1); address-math only.

using u64 = unsigned long long;

// D[i][j] = c_i * cos((2j+1) i pi / 16), c_0 = sqrt(1/8), else 0.5
__device__ constexpr float DMc[8][8] = {
    { 0.3535533905932738f,  0.3535533905932738f,  0.3535533905932738f,  0.3535533905932738f,
      0.3535533905932738f,  0.3535533905932738f,  0.3535533905932738f,  0.3535533905932738f },
    { 0.4903926402016152f,  0.4157348061512726f,  0.2777851165098011f,  0.0975451610080642f,
     -0.0975451610080642f, -0.2777851165098011f, -0.4157348061512726f, -0.4903926402016152f },
    { 0.4619397662556434f,  0.1913417161825449f, -0.1913417161825449f, -0.4619397662556434f,
     -0.4619397662556434f, -0.1913417161825449f,  0.1913417161825449f,  0.4619397662556434f },
    { 0.4157348061512726f, -0.0975451610080642f, -0.4903926402016152f, -0.2777851165098011f,
      0.2777851165098011f,  0.4903926402016152f,  0.0975451610080642f, -0.4157348061512726f },
    { 0.3535533905932738f, -0.3535533905932738f, -0.3535533905932738f,  0.3535533905932738f,
      0.3535533905932738f, -0.3535533905932738f, -0.3535533905932738f,  0.3535533905932738f },
    { 0.2777851165098011f, -0.4903926402016152f,  0.0975451610080642f,  0.4157348061512726f,
     -0.4157348061512726f, -0.0975451610080642f,  0.4903926402016152f, -0.2777851165098011f },
    { 0.1913417161825449f, -0.4619397662556434f,  0.4619397662556434f, -0.1913417161825449f,
     -0.1913417161825449f,  0.4619397662556434f, -0.4619397662556434f,  0.1913417161825449f },
    { 0.0975451610080642f, -0.2777851165098011f,  0.4157348061512726f, -0.4903926402016152f,
      0.4903926402016152f, -0.4157348061512726f,  0.2777851165098011f, -0.0975451610080642f },
};

// quality=50 -> Q == q_luma exactly.
__device__ constexpr float QMc[8][8] = {
    { 16.f, 11.f, 10.f, 16.f,  24.f,  40.f,  51.f,  61.f },
    { 12.f, 12.f, 14.f, 19.f,  26.f,  58.f,  60.f,  55.f },
    { 14.f, 13.f, 16.f, 24.f,  40.f,  57.f,  69.f,  56.f },
    { 14.f, 17.f, 22.f, 29.f,  51.f,  87.f,  80.f,  62.f },
    { 18.f, 22.f, 37.f, 56.f,  68.f, 109.f, 103.f,  77.f },
    { 24.f, 35.f, 55.f, 64.f,  81.f, 104.f, 113.f,  92.f },
    { 49.f, 64.f, 78.f, 87.f, 103.f, 121.f, 120.f, 101.f },
    { 72.f, 92.f, 95.f, 98.f, 112.f, 100.f, 103.f,  99.f },
};

__device__ __forceinline__ u64 pk(float a, float b) {
    u64 r; asm("mov.b64 %0, {%1, %2};" : "=l"(r) : "f"(a), "f"(b)); return r;
}
__device__ __forceinline__ void unpk(float& a, float& b, u64 v) {
    asm("mov.b64 {%0, %1}, %2;" : "=f"(a), "=f"(b) : "l"(v));
}
__device__ __forceinline__ u64 fma2(u64 a, u64 b, u64 c) {
    u64 d; asm("fma.rn.f32x2 %0, %1, %2, %3;" : "=l"(d) : "l"(a), "l"(b), "l"(c)); return d;
}
__device__ __forceinline__ u64 mul2(u64 a, u64 b) {
    u64 d; asm("mul.rn.f32x2 %0, %1, %2;" : "=l"(d) : "l"(a), "l"(b)); return d;
}
__device__ __forceinline__ u64 add2(u64 a, u64 b) {
    u64 d; asm("add.rn.f32x2 %0, %1, %2;" : "=l"(d) : "l"(a), "l"(b)); return d;
}
__device__ __forceinline__ u64 sub2(u64 a, u64 b, u64 neg1) {
    return fma2(b, neg1, a);   // a - b
}

// forward row transform: x pairs -> y = X.D^T pairs (even/odd butterfly)
__device__ __forceinline__ void row_fwd(const u64 (&x)[4], u64 (&y)[4]) {
    float a0,a1,a2,a3,a4,a5,a6,a7;
    unpk(a0, a1, x[0]); unpk(a2, a3, x[1]);
    unpk(a4, a5, x[2]); unpk(a6, a7, x[3]);
    u64 sd[4];
    sd[0] = pk(a0 + a7, a0 - a7);
    sd[1] = pk(a1 + a6, a1 - a6);
    sd[2] = pk(a2 + a5, a2 - a5);
    sd[3] = pk(a3 + a4, a3 - a4);
    #pragma unroll
    for (int t = 0; t < 4; ++t) {
        u64 acc = mul2(sd[0], pk(DMc[2*t][0], DMc[2*t+1][0]));
        #pragma unroll
        for (int j = 1; j < 4; ++j)
            acc = fma2(sd[j], pk(DMc[2*t][j], DMc[2*t+1][j]), acc);
        y[t] = acc;
    }
}

// inverse row transform: w pairs -> o = W.D pairs (even/odd butterfly)
__device__ __forceinline__ void row_inv(const u64 (&w)[4], u64 (&o)[4], u64 NEG1) {
    float m0,m1,m2,m3,m4,m5,m6,m7;
    unpk(m0, m1, w[0]); unpk(m2, m3, w[1]);
    unpk(m4, m5, w[2]); unpk(m6, m7, w[3]);
    u64 U01 = mul2(pk(m0, m0), pk(DMc[0][0], DMc[0][1]));
    u64 U23 = mul2(pk(m0, m0), pk(DMc[0][2], DMc[0][3]));
    u64 V01 = mul2(pk(m1, m1), pk(DMc[1][0], DMc[1][1]));
    u64 V23 = mul2(pk(m1, m1), pk(DMc[1][2], DMc[1][3]));
    const float me[3] = { m2, m4, m6 };
    const float mo[3] = { m3, m5, m7 };
    #pragma unroll
    for (int t = 1; t < 4; ++t) {
        u64 be = pk(me[t-1], me[t-1]);
        U01 = fma2(be, pk(DMc[2*t][0], DMc[2*t][1]), U01);
        U23 = fma2(be, pk(DMc[2*t][2], DMc[2*t][3]), U23);
        u64 bo = pk(mo[t-1], mo[t-1]);
        V01 = fma2(bo, pk(DMc[2*t+1][0], DMc[2*t+1][1]), V01);
        V23 = fma2(bo, pk(DMc[2*t+1][2], DMc[2*t+1][3]), V23);
    }
    o[0] = add2(U01, V01);             // (P0, P1)
    o[1] = add2(U23, V23);             // (P2, P3)
    u64 t76 = sub2(U01, V01, NEG1);    // (P7, P6)
    u64 t54 = sub2(U23, V23, NEG1);    // (P5, P4)
    { float x, y; unpk(x, y, t54); o[2] = pk(y, x); }  // (P4, P5)
    { float x, y; unpk(x, y, t76); o[3] = pk(y, x); }  // (P6, P7)
}

// fused packed quant/dequant of A[8][2] covering columns C..C+3 (compile-time)
template<int C>
__device__ __forceinline__ void quant_cols(u64 (&A)[8][2], u64 NEG1, u64 MAGIC2) {
    #pragma unroll
    for (int i = 0; i < 8; ++i) {
        #pragma unroll
        for (int k = 0; k < 2; ++k) {
            // t = s*(1/Q) + M ; r = t - M ; out = r*Q   (3 packed fma-pipe ops)
            u64 t0 = fma2(A[i][k], pk(1.0f / QMc[i][C+2*k], 1.0f / QMc[i][C+2*k+1]), MAGIC2);
            u64 rr = sub2(t0, MAGIC2, NEG1);
            A[i][k] = mul2(rr, pk(QMc[i][C+2*k], QMc[i][C+2*k+1]));
        }
    }
}

#define PAIR_BAR() asm volatile("bar.sync %0, 64;" :: "r"(pr + 1) : "memory")

__global__ void __launch_bounds__(256, 4)
diffjpeg_kernel(const float* __restrict__ in, float* __restrict__ out, int nblk)
{
    // exchange stage per warp-pair: [row][block(lane)][u64], chunk-swizzled
    __shared__ __align__(16) u64 xb[4][8][32][4];      // 32 KB

    const int tid  = threadIdx.x;
    const int w    = tid >> 5;
    const int lane = tid & 31;
    const int h    = w & 1;          // warp-uniform half
    const int pr   = w >> 1;         // pair id 0..3
    const int sw   = (lane >> 2) & 1;                  // swizzle bit

    int blk = blockIdx.x * 128 + pr * 32 + lane;
    if (blk >= nblk) blk = nblk - 1;                   // duplicate tail: benign

    const u64 NEG1   = pk(-1.0f, -1.0f);
    const u64 MAGIC2 = pk(12582912.0f, 12582912.0f);   // 1.5 * 2^23

    int bw  = blk & 63;
    int t1  = blk >> 6;
    int bh  = t1 & 63;
    int img = t1 >> 6;
    size_t base = ((size_t)img << 18) + ((size_t)bh << 12) + ((size_t)bw << 3);
    const float* p = in  + base;
    float*       q = out + base;

    u64 (*X)[32][4] = xb[pr];
    const int c0 = 2 * sw;          // physical u64 index of logical chunk 0
    const int c1 = 2 * (1 - sw);    // physical u64 index of logical chunk 1

    // ---- load my 4 rows (coalesced), row-fwd, stage to smem (swizzled) ----
    {
        u64 x[4][4];
        #pragma unroll
        for (int r = 0; r < 4; ++r) {
            const ulonglong2* rp =
                reinterpret_cast<const ulonglong2*>(p + (size_t)(4*h + r) * 512);
            ulonglong2 a = __ldcs(rp), b = __ldcs(rp + 1);
            x[r][0] = a.x; x[r][1] = a.y; x[r][2] = b.x; x[r][3] = b.y;
        }
        #pragma unroll
        for (int r = 0; r < 4; ++r) {
            u64 y[4];
            row_fwd(x[r], y);
            *reinterpret_cast<ulonglong2*>(&X[4*h + r][lane][c0]) = make_ulonglong2(y[0], y[1]);
            *reinterpret_cast<ulonglong2*>(&X[4*h + r][lane][c1]) = make_ulonglong2(y[2], y[3]);
        }
    }
    PAIR_BAR();

    // ---- col-split middle: col-fwd butterfly over rows --------------------
    const int ch = 2 * (h ^ sw);                       // my logical chunk h, swizzled
    u64 A[8][2];
    #pragma unroll
    for (int t = 0; t < 4; ++t) {
        ulonglong2 yt = *reinterpret_cast<const ulonglong2*>(&X[t][lane][ch]);
        ulonglong2 yb = *reinterpret_cast<const ulonglong2*>(&X[7 - t][lane][ch]);
        u64 S0 = add2(yt.x, yb.x),       S1 = add2(yt.y, yb.y);
        u64 D0 = sub2(yt.x, yb.x, NEG1), D1 = sub2(yt.y, yb.y, NEG1);
        #pragma unroll
        for (int u = 0; u < 4; ++u) {
            u64 ce = pk(DMc[2*u][t],   DMc[2*u][t]);
            u64 co = pk(DMc[2*u+1][t], DMc[2*u+1][t]);
            if (t == 0) {
                A[2*u][0]   = mul2(ce, S0);  A[2*u][1]   = mul2(ce, S1);
                A[2*u+1][0] = mul2(co, D0);  A[2*u+1][1] = mul2(co, D1);
            } else {
                A[2*u][0]   = fma2(ce, S0, A[2*u][0]);   A[2*u][1]   = fma2(ce, S1, A[2*u][1]);
                A[2*u+1][0] = fma2(co, D0, A[2*u+1][0]); A[2*u+1][1] = fma2(co, D1, A[2*u+1][1]);
            }
        }
    }
    PAIR_BAR();                                        // all reads done before rewrite

    // ---- quant/dequant: columns 4h..4h+3, constants are immediates --------
    if (h == 0) quant_cols<0>(A, NEG1, MAGIC2);
    else        quant_cols<4>(A, NEG1, MAGIC2);

    // ---- col-inv butterfly, write rows back to stage ----------------------
    #pragma unroll
    for (int i = 0; i < 4; ++i) {
        u64 u0, u1, v0, v1;
        {
            u64 ce = pk(DMc[0][i], DMc[0][i]);
            u64 co = pk(DMc[1][i], DMc[1][i]);
            u0 = mul2(ce, A[0][0]); u1 = mul2(ce, A[0][1]);
            v0 = mul2(co, A[1][0]); v1 = mul2(co, A[1][1]);
        }
        #pragma unroll
        for (int t = 1; t < 4; ++t) {
            u64 ce = pk(DMc[2*t][i], DMc[2*t][i]);
            u64 co = pk(DMc[2*t+1][i], DMc[2*t+1][i]);
            u0 = fma2(ce, A[2*t][0], u0);   u1 = fma2(ce, A[2*t][1], u1);
            v0 = fma2(co, A[2*t+1][0], v0); v1 = fma2(co, A[2*t+1][1], v1);
        }
        *reinterpret_cast<ulonglong2*>(&X[i][lane][ch]) =
            make_ulonglong2(add2(u0, v0), add2(u1, v1));
        *reinterpret_cast<ulonglong2*>(&X[7 - i][lane][ch]) =
            make_ulonglong2(sub2(u0, v0, NEG1), sub2(u1, v1, NEG1));
    }
    PAIR_BAR();

    // ---- back to row-split: row-inv my 4 rows, store coalesced ------------
    #pragma unroll
    for (int r = 0; r < 4; ++r) {
        ulonglong2 wa = *reinterpret_cast<const ulonglong2*>(&X[4*h + r][lane][c0]);
        ulonglong2 wb = *reinterpret_cast<const ulonglong2*>(&X[4*h + r][lane][c1]);
        u64 wrow[4] = { wa.x, wa.y, wb.x, wb.y };
        u64 o[4];
        row_inv(wrow, o, NEG1);
        ulonglong2* op = reinterpret_cast<ulonglong2*>(q + (size_t)(4*h + r) * 512);
        __stcs(op,     make_ulonglong2(o[0], o[1]));
        __stcs(op + 1, make_ulonglong2(o[2], o[3]));
    }
}

extern "C" void kernel_launch(void* const* d_in, const int* in_sizes, int n_in,
                              void* d_out, int out_size)
{
    const float* in  = (const float*)d_in[0];
    float*       out = (float*)d_out;
    int nblk = in_sizes[0] / 64;                  // number of 8x8 blocks
    int grid = (nblk + 127) / 128;                // 128 blocks per CTA (4 warp-pairs)
    diffjpeg_kernel<<<grid, 256>>>(in, out, nblk);
}